// round 16
// baseline (speedup 1.0000x reference)
#include <cuda_runtime.h>
#include <cuda_bf16.h>
#include <cstdint>

#define MTOK 8192
#define D0   2048
#define D1   8192
#define NW   (D0*D1)
#define EPSF 1e-5f
#define MHALF 4096

__device__ __align__(1024) int8_t g_xq [MTOK*(size_t)D0];     // 16 MB
__device__ __align__(1024) int8_t g_w1q[(size_t)NW];          // 16 MB
__device__ __align__(1024) int8_t g_w2q[(size_t)NW];          // 16 MB
__device__ __align__(1024) float  g_h  [67108864];            // 256 MB
__device__ float g_inv_s1[MTOK];
__device__ float g_oscale[MTOK];
__device__ float g_rowmax[MTOK];
__device__ float g_t2[MTOK];
__device__ float g_s2a[MTOK];
__device__ float g_wpart[2*1024];
__device__ float g_invsw[2];

__device__ __forceinline__ uint32_t smem_u32(const void* p) {
    uint32_t a;
    asm("{ .reg .u64 t; cvta.to.shared.u64 t, %1; cvt.u32.u64 %0, t; }" : "=r"(a) : "l"(p));
    return a;
}
__device__ __forceinline__ void cp16(uint32_t s, const void* g) {
    asm volatile("cp.async.cg.shared.global [%0], [%1], 16;" :: "r"(s), "l"(g));
}
__device__ __forceinline__ void ldsm4(uint32_t addr, uint32_t* r) {
    asm volatile("ldmatrix.sync.aligned.m8n8.x4.shared.b16 {%0,%1,%2,%3}, [%4];"
        : "=r"(r[0]), "=r"(r[1]), "=r"(r[2]), "=r"(r[3]) : "r"(addr));
}
__device__ __forceinline__ void mma_s8(int* c, const uint32_t* a, const uint32_t* b) {
    asm volatile("mma.sync.aligned.m16n8k32.row.col.s32.s8.s8.s32 "
        "{%0,%1,%2,%3}, {%4,%5,%6,%7}, {%8,%9}, {%0,%1,%2,%3};"
        : "+r"(c[0]), "+r"(c[1]), "+r"(c[2]), "+r"(c[3])
        : "r"(a[0]), "r"(a[1]), "r"(a[2]), "r"(a[3]), "r"(b[0]), "r"(b[1]));
}

__device__ __forceinline__ float blockMax256(float v) {
    __shared__ float sh[8];
    #pragma unroll
    for (int o = 16; o; o >>= 1) v = fmaxf(v, __shfl_xor_sync(~0u, v, o));
    if ((threadIdx.x & 31) == 0) sh[threadIdx.x >> 5] = v;
    __syncthreads();
    if (threadIdx.x < 32) {
        float t = (threadIdx.x < 8) ? sh[threadIdx.x] : 0.f;
        #pragma unroll
        for (int o = 4; o; o >>= 1) t = fmaxf(t, __shfl_xor_sync(~0u, t, o));
        if (threadIdx.x == 0) sh[0] = t;
    }
    __syncthreads();
    return sh[0];
}

__device__ __forceinline__ uint32_t pack_s8(float a, float b, float c, float d) {
    return (uint32_t)((int)a & 0xff) | (((uint32_t)((int)b & 0xff)) << 8) |
           (((uint32_t)((int)c & 0xff)) << 16) | (((uint32_t)((int)d & 0xff)) << 24);
}

// ---------------- quantization kernels ----------------
__global__ void absmean_partial(const float* __restrict__ w, int slot) {
    __shared__ float sh[256];
    const float4* p = (const float4*)w;
    float s = 0.f;
    for (int i = blockIdx.x * 256 + threadIdx.x; i < (NW >> 2); i += 1024 * 256) {
        float4 v = p[i];
        s += fabsf(v.x) + fabsf(v.y) + fabsf(v.z) + fabsf(v.w);
    }
    sh[threadIdx.x] = s; __syncthreads();
    for (int o = 128; o; o >>= 1) { if (threadIdx.x < o) sh[threadIdx.x] += sh[threadIdx.x + o]; __syncthreads(); }
    if (threadIdx.x == 0) g_wpart[slot * 1024 + blockIdx.x] = sh[0];
}

// wquant with folded finalize (bit-identical; validated R12-R15).
__global__ void wquant(const float* __restrict__ w, int8_t* __restrict__ wq, int slot) {
    __shared__ float sh[256];
    const int tid = threadIdx.x;
    const float* part = g_wpart + slot * 1024;
    float s = ((part[tid] + part[tid + 256]) + part[tid + 512]) + part[tid + 768];
    sh[tid] = s; __syncthreads();
    for (int o = 128; o; o >>= 1) { if (tid < o) sh[tid] += sh[tid + o]; __syncthreads(); }
    const float mean = fmaxf(sh[0] / (float)NW, EPSF);
    if (blockIdx.x == 0 && tid == 0) g_invsw[slot] = mean;
    const float ws = 1.0f / mean;

    const int base = blockIdx.x * 512 + tid;
    const float4* p = (const float4*)w;
    float4 a = p[base], b = p[base + 256];
    float qa[4] = {a.x, a.y, a.z, a.w}, qb[4] = {b.x, b.y, b.z, b.w};
    #pragma unroll
    for (int k = 0; k < 4; k++) {
        qa[k] = fminf(fmaxf(rintf(qa[k] * ws), -1.f), 1.f);
        qb[k] = fminf(fmaxf(rintf(qb[k] * ws), -1.f), 1.f);
    }
    uint32_t* dst = (uint32_t*)wq;
    dst[base]       = pack_s8(qa[0], qa[1], qa[2], qa[3]);
    dst[base + 256] = pack_s8(qb[0], qb[1], qb[2], qb[3]);
}

__global__ void xquant(const float* __restrict__ x) {
    const int row = blockIdx.x, tid = threadIdx.x;
    const float4* xp = (const float4*)(x + (size_t)row * D0);
    float4 a = xp[tid], b = xp[tid + 256];
    float m = fmaxf(fmaxf(fabsf(a.x), fabsf(a.y)), fmaxf(fabsf(a.z), fabsf(a.w)));
    m = fmaxf(m, fmaxf(fmaxf(fabsf(b.x), fabsf(b.y)), fmaxf(fabsf(b.z), fabsf(b.w))));
    m = blockMax256(m);
    __shared__ float s_sc;
    if (tid == 0) {
        float cm = fmaxf(m, EPSF);
        s_sc = 127.0f / cm;
        g_inv_s1[row] = cm / 127.0f;
    }
    __syncthreads();
    float sc = s_sc;
    float qa[4] = {a.x, a.y, a.z, a.w}, qb[4] = {b.x, b.y, b.z, b.w};
    #pragma unroll
    for (int k = 0; k < 4; k++) {
        qa[k] = fminf(fmaxf(rintf(qa[k] * sc), -128.f), 127.f);
        qb[k] = fminf(fmaxf(rintf(qb[k] * sc), -128.f), 127.f);
    }
    uint32_t* dst = (uint32_t*)(g_xq + (size_t)row * D0);
    dst[tid]       = pack_s8(qa[0], qa[1], qa[2], qa[3]);
    dst[tid + 256] = pack_s8(qb[0], qb[1], qb[2], qb[3]);
}

// hscale: per-row scale factors from gemm1's atomicMax rowmax.
// Identical math to old hquant's per-row preamble -> bit-identical scales.
__global__ void hscale() {
    const int row = blockIdx.x * 256 + threadIdx.x;
    const float t = g_inv_s1[row] * g_invsw[0];
    const float cm = fmaxf(g_rowmax[row] * t, EPSF);
    g_t2[row] = t;
    g_s2a[row] = 127.0f / cm;
    g_oscale[row] = (cm / 127.0f) * g_invsw[1];
}

// ---------------- gemm1: int8 TC GEMM, raw fp32 out + rowmax atomics --------
#define BM 128
#define BN 256
#define BKK 128
#define ROWB 144
#define STG 3
#define ST_BYTES ((BM + BN) * ROWB)          // 55296
#define GEMM_SMEM (STG * ST_BYTES)           // 165888

__global__ void __launch_bounds__(576, 1)
gemm_s8(const int8_t* __restrict__ A, const int8_t* __restrict__ B,
        float* __restrict__ C, int K, int N, int moff)
{
    extern __shared__ char smem[];
    const uint32_t sb = smem_u32(smem);
    const int t = threadIdx.x, l = t & 31, w = t >> 5;
    const int m0 = moff + blockIdx.y * BM, n0 = blockIdx.x * BN;
    const int wm = (w & 1) * 64, wn = (w >> 1) * 32;

    const int arow = t >> 3, acol = (t & 7) * 16;
    const int8_t* gA = A + (size_t)(m0 + arow) * K + acol;
    const int8_t* gB = B + (size_t)(n0 + arow) * K + acol;
    const uint32_t sAo = arow * ROWB + acol;
    const uint32_t sBo = BM * ROWB + arow * ROWB + acol;

    const int nk = K / BKK;

    #pragma unroll
    for (int s = 0; s < STG - 1; s++) {
        const uint32_t st = sb + s * ST_BYTES;
        const int k0 = s * BKK;
        #pragma unroll
        for (int p = 0; p < 2; p++)
            cp16(st + sAo + p * 64 * ROWB, gA + (size_t)(p * 64) * K + k0);
        #pragma unroll
        for (int p = 0; p < 4; p++)
            cp16(st + sBo + p * 64 * ROWB, gB + (size_t)(p * 64) * K + k0);
        asm volatile("cp.async.commit_group;" ::: "memory");
    }

    int acc[4][4][4];
    #pragma unroll
    for (int mi = 0; mi < 4; mi++)
        #pragma unroll
        for (int ni = 0; ni < 4; ni++)
            #pragma unroll
            for (int c = 0; c < 4; c++) acc[mi][ni][c] = 0;

    const uint32_t aBase = (uint32_t)(wm + (l % 16)) * ROWB + (l / 16) * 16;
    const uint32_t bBase = BM * ROWB +
        (uint32_t)(wn + (l & 7) + ((l >> 4) & 1) * 8) * ROWB + ((l >> 3) & 1) * 16;

    for (int i = 0; i < nk; i++) {
        asm volatile("cp.async.wait_group %0;" :: "n"(STG - 2));
        __syncthreads();

        const int j = i + STG - 1;
        if (j < nk) {
            const uint32_t st = sb + (j % STG) * ST_BYTES;
            const int k0 = j * BKK;
            #pragma unroll
            for (int p = 0; p < 2; p++)
                cp16(st + sAo + p * 64 * ROWB, gA + (size_t)(p * 64) * K + k0);
            #pragma unroll
            for (int p = 0; p < 4; p++)
                cp16(st + sBo + p * 64 * ROWB, gB + (size_t)(p * 64) * K + k0);
        }
        asm volatile("cp.async.commit_group;" ::: "memory");

        const uint32_t st = sb + (i % STG) * ST_BYTES;
        #pragma unroll
        for (int ksub = 0; ksub < 4; ksub++) {
            uint32_t aF[4][4], bR[2][4];
            const uint32_t ka = st + aBase + ksub * 32;
            const uint32_t kb = st + bBase + ksub * 32;
            #pragma unroll
            for (int mi = 0; mi < 4; mi++) ldsm4(ka + mi * 16 * ROWB, aF[mi]);
            #pragma unroll
            for (int nq = 0; nq < 2; nq++) ldsm4(kb + nq * 16 * ROWB, bR[nq]);
            #pragma unroll
            for (int mi = 0; mi < 4; mi++)
                #pragma unroll
                for (int nq = 0; nq < 2; nq++) {
                    mma_s8(acc[mi][nq * 2],     aF[mi], &bR[nq][0]);
                    mma_s8(acc[mi][nq * 2 + 1], aF[mi], &bR[nq][2]);
                }
        }
    }

    // epilogue: raw stores + per-row relu-max via atomicMax (values >= 0, so
    // float-as-int atomicMax is exact; max is order-independent -> bit-identical)
    #pragma unroll
    for (int mi = 0; mi < 4; mi++) {
        const int r0 = m0 + wm + mi * 16 + (l >> 2);
        float mx0 = 0.f, mx1 = 0.f;
        #pragma unroll
        for (int ni = 0; ni < 4; ni++) {
            const int c = n0 + wn + ni * 8 + (l & 3) * 2;
            float v0x = (float)acc[mi][ni][0], v0y = (float)acc[mi][ni][1];
            float v1x = (float)acc[mi][ni][2], v1y = (float)acc[mi][ni][3];
            mx0 = fmaxf(mx0, fmaxf(v0x, v0y));
            mx1 = fmaxf(mx1, fmaxf(v1x, v1y));
            *(float2*)(C + (size_t)r0 * N + c)       = make_float2(v0x, v0y);
            *(float2*)(C + (size_t)(r0 + 8) * N + c) = make_float2(v1x, v1y);
        }
        mx0 = fmaxf(mx0, __shfl_xor_sync(~0u, mx0, 1));
        mx0 = fmaxf(mx0, __shfl_xor_sync(~0u, mx0, 2));
        mx1 = fmaxf(mx1, __shfl_xor_sync(~0u, mx1, 1));
        mx1 = fmaxf(mx1, __shfl_xor_sync(~0u, mx1, 2));
        if ((l & 3) == 0) {
            atomicMax((int*)&g_rowmax[r0],     __float_as_int(mx0));
            atomicMax((int*)&g_rowmax[r0 + 8], __float_as_int(mx1));
        }
    }
}

// ---------------- gemm2: fused A-quantize from fp32 h ----------------------
// A-tiles read fp32 from g_h, quantized inline (pipelined one iter ahead in
// registers), stored s8 to the same smem layout. B keeps cp.async. Quantize
// expression order identical to old hquant -> bit-identical mma inputs.
__global__ void __launch_bounds__(512, 1)
gemm2_fused(const float* __restrict__ A, const int8_t* __restrict__ B,
            float* __restrict__ C, int K, int N)
{
    extern __shared__ char smem[];
    const uint32_t sb = smem_u32(smem);
    const int t = threadIdx.x, l = t & 31, w = t >> 5;
    const int m0 = blockIdx.y * BM, n0 = blockIdx.x * BN;
    const int wm = (w & 1) * 64, wn = (w >> 1) * 32;

    const int brow = t >> 3, bcol = (t & 7) * 16;
    const int8_t* gB = B + (size_t)(n0 + brow) * K + bcol;
    const uint32_t sBo = BM * ROWB + brow * ROWB + bcol;

    const int nk = K / BKK;   // 64

    float4 aReg[8];
    // prologue: A stage0 -> regs -> smem; A stage1 -> regs; B stages 0,1
    #pragma unroll
    for (int p = 0; p < 8; p++)
        aReg[p] = *(const float4*)(A + (size_t)(m0 + p * 16 + w) * K + l * 4);
    #pragma unroll
    for (int p = 0; p < 8; p++) {
        const int row = p * 16 + w;
        const float tq = g_t2[m0 + row], sq = g_s2a[m0 + row];
        float4 v = aReg[p];
        uint32_t qw = pack_s8(
            fminf(rintf(fmaxf(v.x, 0.f) * tq * sq), 127.f),
            fminf(rintf(fmaxf(v.y, 0.f) * tq * sq), 127.f),
            fminf(rintf(fmaxf(v.z, 0.f) * tq * sq), 127.f),
            fminf(rintf(fmaxf(v.w, 0.f) * tq * sq), 127.f));
        asm volatile("st.shared.u32 [%0], %1;" :: "r"(sb + row * ROWB + l * 4), "r"(qw) : "memory");
    }
    #pragma unroll
    for (int p = 0; p < 8; p++)
        aReg[p] = *(const float4*)(A + (size_t)(m0 + p * 16 + w) * K + BKK + l * 4);
    #pragma unroll
    for (int s = 0; s < 2; s++) {
        const uint32_t st = sb + s * ST_BYTES;
        #pragma unroll
        for (int p = 0; p < 4; p++)
            cp16(st + sBo + p * 64 * ROWB, gB + (size_t)(p * 64) * K + s * BKK);
        asm volatile("cp.async.commit_group;" ::: "memory");
    }

    int acc[4][4][4];
    #pragma unroll
    for (int mi = 0; mi < 4; mi++)
        #pragma unroll
        for (int ni = 0; ni < 4; ni++)
            #pragma unroll
            for (int c = 0; c < 4; c++) acc[mi][ni][c] = 0;

    const uint32_t aBase = (uint32_t)(wm + (l % 16)) * ROWB + (l / 16) * 16;
    const uint32_t bBase = BM * ROWB +
        (uint32_t)(wn + (l & 7) + ((l >> 4) & 1) * 8) * ROWB + ((l >> 3) & 1) * 16;

    for (int i = 0; i < nk; i++) {
        asm volatile("cp.async.wait_group 1;" ::: "memory");
        __syncthreads();

        if (i + 1 < nk) {   // publish A stage i+1 (regs loaded last iter)
            const uint32_t stn = sb + ((i + 1) % 3) * ST_BYTES;
            #pragma unroll
            for (int p = 0; p < 8; p++) {
                const int row = p * 16 + w;
                const float tq = g_t2[m0 + row], sq = g_s2a[m0 + row];
                float4 v = aReg[p];
                uint32_t qw = pack_s8(
                    fminf(rintf(fmaxf(v.x, 0.f) * tq * sq), 127.f),
                    fminf(rintf(fmaxf(v.y, 0.f) * tq * sq), 127.f),
                    fminf(rintf(fmaxf(v.z, 0.f) * tq * sq), 127.f),
                    fminf(rintf(fmaxf(v.w, 0.f) * tq * sq), 127.f));
                asm volatile("st.shared.u32 [%0], %1;" :: "r"(stn + row * ROWB + l * 4), "r"(qw) : "memory");
            }
        }
        if (i + 2 < nk) {   // prefetch A regs + B cp.async for stage i+2
            #pragma unroll
            for (int p = 0; p < 8; p++)
                aReg[p] = *(const float4*)(A + (size_t)(m0 + p * 16 + w) * K + (i + 2) * BKK + l * 4);
            const uint32_t st2 = sb + ((i + 2) % 3) * ST_BYTES;
            #pragma unroll
            for (int p = 0; p < 4; p++)
                cp16(st2 + sBo + p * 64 * ROWB, gB + (size_t)(p * 64) * K + (i + 2) * BKK);
        }
        asm volatile("cp.async.commit_group;" ::: "memory");

        const uint32_t st = sb + (i % 3) * ST_BYTES;
        #pragma unroll
        for (int ksub = 0; ksub < 4; ksub++) {
            uint32_t aF[4][4], bR[2][4];
            const uint32_t ka = st + aBase + ksub * 32;
            const uint32_t kb = st + bBase + ksub * 32;
            #pragma unroll
            for (int mi = 0; mi < 4; mi++) ldsm4(ka + mi * 16 * ROWB, aF[mi]);
            #pragma unroll
            for (int nq = 0; nq < 2; nq++) ldsm4(kb + nq * 16 * ROWB, bR[nq]);
            #pragma unroll
            for (int mi = 0; mi < 4; mi++)
                #pragma unroll
                for (int nq = 0; nq < 2; nq++) {
                    mma_s8(acc[mi][nq * 2],     aF[mi], &bR[nq][0]);
                    mma_s8(acc[mi][nq * 2 + 1], aF[mi], &bR[nq][2]);
                }
        }
    }

    #pragma unroll
    for (int mi = 0; mi < 4; mi++) {
        const int r0 = m0 + wm + mi * 16 + (l >> 2);
        const float sc0 = g_oscale[r0];
        const float sc1 = g_oscale[r0 + 8];
        #pragma unroll
        for (int ni = 0; ni < 4; ni++) {
            const int c = n0 + wn + ni * 8 + (l & 3) * 2;
            float2 v0 = make_float2((float)acc[mi][ni][0] * sc0, (float)acc[mi][ni][1] * sc0);
            float2 v1 = make_float2((float)acc[mi][ni][2] * sc1, (float)acc[mi][ni][3] * sc1);
            *(float2*)(C + (size_t)r0 * N + c)       = v0;
            *(float2*)(C + (size_t)(r0 + 8) * N + c) = v1;
        }
    }
}

// ---------------- host ----------------
extern "C" void kernel_launch(void* const* d_in, const int* in_sizes, int n_in,
                              void* d_out, int out_size) {
    const float* x  = (const float*)d_in[0];
    const float* w1 = (const float*)d_in[1];
    const float* w2 = (const float*)d_in[2];
    float* out = (float*)d_out;

    void *pxq, *pw1q, *pw2q, *ph, *prm;
    cudaGetSymbolAddress(&pxq, g_xq);
    cudaGetSymbolAddress(&pw1q, g_w1q);
    cudaGetSymbolAddress(&pw2q, g_w2q);
    cudaGetSymbolAddress(&ph, g_h);
    cudaGetSymbolAddress(&prm, g_rowmax);

    cudaFuncSetAttribute(gemm_s8, cudaFuncAttributeMaxDynamicSharedMemorySize, GEMM_SMEM);
    cudaFuncSetAttribute(gemm2_fused, cudaFuncAttributeMaxDynamicSharedMemorySize, GEMM_SMEM);

    cudaStream_t S = cudaStreamPerThread;
    cudaEvent_t eFork, eX, eW2;
    cudaEventCreateWithFlags(&eFork, cudaEventDisableTiming);
    cudaEventCreateWithFlags(&eX,  cudaEventDisableTiming);
    cudaEventCreateWithFlags(&eW2, cudaEventDisableTiming);

    // rowmax must be zero before gemm1 (graph-legal memset node)
    cudaMemsetAsync(prm, 0, MTOK * sizeof(float), 0);

    // fork side stream: xquant, then w2 chain
    cudaEventRecord(eFork, 0);
    cudaStreamWaitEvent(S, eFork, 0);
    xquant<<<MTOK, 256, 0, S>>>(x);
    cudaEventRecord(eX, S);
    absmean_partial<<<1024, 256, 0, S>>>(w2, 1);
    wquant<<<NW / (512 * 4), 256, 0, S>>>(w2, (int8_t*)pw2q, 1);
    cudaEventRecord(eW2, S);

    // main: w1 chain, gemm1 halves (raw out + rowmax)
    absmean_partial<<<1024, 256>>>(w1, 0);
    wquant<<<NW / (512 * 4), 256>>>(w1, (int8_t*)pw1q, 0);
    cudaStreamWaitEvent(0, eX, 0);
    gemm_s8<<<dim3(D1 / BN, MHALF / BM), 512, GEMM_SMEM>>>(
        (const int8_t*)pxq, (const int8_t*)pw1q, (float*)ph, D0, D1, 0);
    gemm_s8<<<dim3(D1 / BN, MHALF / BM), 512, GEMM_SMEM>>>(
        (const int8_t*)pxq, (const int8_t*)pw1q, (float*)ph, D0, D1, MHALF);

    // scales (needs rowmax + invsw[1]) then fused gemm2
    cudaStreamWaitEvent(0, eW2, 0);
    hscale<<<MTOK / 256, 256>>>();
    gemm2_fused<<<dim3(D0 / BN, MTOK / BM), 512, GEMM_SMEM>>>(
        (const float*)ph, (const int8_t*)pw2q, out, D1, D0);
}

// round 17
// speedup vs baseline: 1.3067x; 1.3067x over previous
#include <cuda_runtime.h>
#include <cuda_bf16.h>
#include <cstdint>

#define MTOK 8192
#define D0   2048
#define D1   8192
#define NW   (D0*D1)
#define EPSF 1e-5f

__device__ __align__(1024) int8_t g_xq [MTOK*(size_t)D0];     // 16 MB
__device__ __align__(1024) int8_t g_w1q[(size_t)NW];          // 16 MB
__device__ __align__(1024) int8_t g_w2q[(size_t)NW];          // 16 MB
__device__ __align__(1024) float  g_h  [67108864];            // 256 MB
__device__ __align__(1024) int8_t g_hq [67108864];            // 64 MB
__device__ float g_inv_s1[MTOK];
__device__ float g_oscale[MTOK];
__device__ float g_wpart[2*1024];
__device__ float g_invsw[2];

__device__ __forceinline__ uint32_t smem_u32(const void* p) {
    uint32_t a;
    asm("{ .reg .u64 t; cvta.to.shared.u64 t, %1; cvt.u32.u64 %0, t; }" : "=r"(a) : "l"(p));
    return a;
}
__device__ __forceinline__ void cp16(uint32_t s, const void* g) {
    asm volatile("cp.async.cg.shared.global [%0], [%1], 16;" :: "r"(s), "l"(g));
}
__device__ __forceinline__ void ldsm4(uint32_t addr, uint32_t* r) {
    asm volatile("ldmatrix.sync.aligned.m8n8.x4.shared.b16 {%0,%1,%2,%3}, [%4];"
        : "=r"(r[0]), "=r"(r[1]), "=r"(r[2]), "=r"(r[3]) : "r"(addr));
}
__device__ __forceinline__ void mma_s8(int* c, const uint32_t* a, const uint32_t* b) {
    asm volatile("mma.sync.aligned.m16n8k32.row.col.s32.s8.s8.s32 "
        "{%0,%1,%2,%3}, {%4,%5,%6,%7}, {%8,%9}, {%0,%1,%2,%3};"
        : "+r"(c[0]), "+r"(c[1]), "+r"(c[2]), "+r"(c[3])
        : "r"(a[0]), "r"(a[1]), "r"(a[2]), "r"(a[3]), "r"(b[0]), "r"(b[1]));
}

__device__ __forceinline__ float blockMax256(float v) {
    __shared__ float sh[8];
    #pragma unroll
    for (int o = 16; o; o >>= 1) v = fmaxf(v, __shfl_xor_sync(~0u, v, o));
    if ((threadIdx.x & 31) == 0) sh[threadIdx.x >> 5] = v;
    __syncthreads();
    if (threadIdx.x < 32) {
        float t = (threadIdx.x < 8) ? sh[threadIdx.x] : 0.f;
        #pragma unroll
        for (int o = 4; o; o >>= 1) t = fmaxf(t, __shfl_xor_sync(~0u, t, o));
        if (threadIdx.x == 0) sh[0] = t;
    }
    __syncthreads();
    return sh[0];
}

__device__ __forceinline__ uint32_t pack_s8(float a, float b, float c, float d) {
    return (uint32_t)((int)a & 0xff) | (((uint32_t)((int)b & 0xff)) << 8) |
           (((uint32_t)((int)c & 0xff)) << 16) | (((uint32_t)((int)d & 0xff)) << 24);
}

// ---------------- quantization kernels ----------------
__global__ void absmean_partial(const float* __restrict__ w, int slot) {
    __shared__ float sh[256];
    const float4* p = (const float4*)w;
    float s = 0.f;
    for (int i = blockIdx.x * 256 + threadIdx.x; i < (NW >> 2); i += 1024 * 256) {
        float4 v = p[i];
        s += fabsf(v.x) + fabsf(v.y) + fabsf(v.z) + fabsf(v.w);
    }
    sh[threadIdx.x] = s; __syncthreads();
    for (int o = 128; o; o >>= 1) { if (threadIdx.x < o) sh[threadIdx.x] += sh[threadIdx.x + o]; __syncthreads(); }
    if (threadIdx.x == 0) g_wpart[slot * 1024 + blockIdx.x] = sh[0];
}

// wquant with folded finalize (bit-identical; validated R12-R16).
__global__ void wquant(const float* __restrict__ w, int8_t* __restrict__ wq, int slot) {
    __shared__ float sh[256];
    const int tid = threadIdx.x;
    const float* part = g_wpart + slot * 1024;
    float s = ((part[tid] + part[tid + 256]) + part[tid + 512]) + part[tid + 768];
    sh[tid] = s; __syncthreads();
    for (int o = 128; o; o >>= 1) { if (tid < o) sh[tid] += sh[tid + o]; __syncthreads(); }
    const float mean = fmaxf(sh[0] / (float)NW, EPSF);
    if (blockIdx.x == 0 && tid == 0) g_invsw[slot] = mean;
    const float ws = 1.0f / mean;

    const int base = blockIdx.x * 512 + tid;
    const float4* p = (const float4*)w;
    float4 a = p[base], b = p[base + 256];
    float qa[4] = {a.x, a.y, a.z, a.w}, qb[4] = {b.x, b.y, b.z, b.w};
    #pragma unroll
    for (int k = 0; k < 4; k++) {
        qa[k] = fminf(fmaxf(rintf(qa[k] * ws), -1.f), 1.f);
        qb[k] = fminf(fmaxf(rintf(qb[k] * ws), -1.f), 1.f);
    }
    uint32_t* dst = (uint32_t*)wq;
    dst[base]       = pack_s8(qa[0], qa[1], qa[2], qa[3]);
    dst[base + 256] = pack_s8(qb[0], qb[1], qb[2], qb[3]);
}

__global__ void xquant(const float* __restrict__ x) {
    const int row = blockIdx.x, tid = threadIdx.x;
    const float4* xp = (const float4*)(x + (size_t)row * D0);
    float4 a = xp[tid], b = xp[tid + 256];
    float m = fmaxf(fmaxf(fabsf(a.x), fabsf(a.y)), fmaxf(fabsf(a.z), fabsf(a.w)));
    m = fmaxf(m, fmaxf(fmaxf(fabsf(b.x), fabsf(b.y)), fmaxf(fabsf(b.z), fabsf(b.w))));
    m = blockMax256(m);
    __shared__ float s_sc;
    if (tid == 0) {
        float cm = fmaxf(m, EPSF);
        s_sc = 127.0f / cm;
        g_inv_s1[row] = cm / 127.0f;
    }
    __syncthreads();
    float sc = s_sc;
    float qa[4] = {a.x, a.y, a.z, a.w}, qb[4] = {b.x, b.y, b.z, b.w};
    #pragma unroll
    for (int k = 0; k < 4; k++) {
        qa[k] = fminf(fmaxf(rintf(qa[k] * sc), -128.f), 127.f);
        qb[k] = fminf(fmaxf(rintf(qb[k] * sc), -128.f), 127.f);
    }
    uint32_t* dst = (uint32_t*)(g_xq + (size_t)row * D0);
    dst[tid]       = pack_s8(qa[0], qa[1], qa[2], qa[3]);
    dst[tid + 256] = pack_s8(qb[0], qb[1], qb[2], qb[3]);
}

// single-pass hquant (R13/R14-validated form)
__global__ void hquant() {
    const int row = blockIdx.x, tid = threadIdx.x;
    const float4* hp = (const float4*)(g_h + (size_t)row * D1);
    float4 v[8];
    float m = 0.f;
    #pragma unroll
    for (int i = 0; i < 8; i++) {
        v[i] = hp[tid + 256 * i];
        m = fmaxf(m, fmaxf(fmaxf(v[i].x, v[i].y), fmaxf(v[i].z, v[i].w)));
    }
    m = blockMax256(m);
    __shared__ float s_s2, s_t;
    if (tid == 0) {
        float t = g_inv_s1[row] * g_invsw[0];
        float cm = fmaxf(m * t, EPSF);
        s_s2 = 127.0f / cm; s_t = t;
        g_oscale[row] = (cm / 127.0f) * g_invsw[1];
    }
    __syncthreads();
    float s2 = s_s2, t = s_t;
    uint32_t* dst = (uint32_t*)(g_hq + (size_t)row * D1);
    #pragma unroll
    for (int i = 0; i < 8; i++) {
        float q0 = fminf(rintf(fmaxf(v[i].x, 0.f) * t * s2), 127.f);
        float q1 = fminf(rintf(fmaxf(v[i].y, 0.f) * t * s2), 127.f);
        float q2 = fminf(rintf(fmaxf(v[i].z, 0.f) * t * s2), 127.f);
        float q3 = fminf(rintf(fmaxf(v[i].w, 0.f) * t * s2), 127.f);
        dst[tid + 256 * i] = pack_s8(q0, q1, q2, q3);
    }
}

// ---------------- int8 tensor-core GEMM (R13/R14 body, full-M grid) --------
#define BM 128
#define BN 256
#define BKK 128
#define ROWB 144
#define STG 3
#define ST_BYTES ((BM + BN) * ROWB)          // 55296
#define GEMM_SMEM (STG * ST_BYTES)           // 165888

__global__ void __launch_bounds__(576, 1)
gemm_s8(const int8_t* __restrict__ A, const int8_t* __restrict__ B,
        float* __restrict__ C, int K, int N, int mode)
{
    extern __shared__ char smem[];
    const uint32_t sb = smem_u32(smem);
    const int t = threadIdx.x, l = t & 31, w = t >> 5;
    const int m0 = blockIdx.y * BM, n0 = blockIdx.x * BN;
    const int wm = (w & 1) * 64, wn = (w >> 1) * 32;

    const int arow = t >> 3, acol = (t & 7) * 16;
    const int8_t* gA = A + (size_t)(m0 + arow) * K + acol;
    const int8_t* gB = B + (size_t)(n0 + arow) * K + acol;
    const uint32_t sAo = arow * ROWB + acol;
    const uint32_t sBo = BM * ROWB + arow * ROWB + acol;

    const int nk = K / BKK;

    #pragma unroll
    for (int s = 0; s < STG - 1; s++) {
        const uint32_t st = sb + s * ST_BYTES;
        const int k0 = s * BKK;
        #pragma unroll
        for (int p = 0; p < 2; p++)
            cp16(st + sAo + p * 64 * ROWB, gA + (size_t)(p * 64) * K + k0);
        #pragma unroll
        for (int p = 0; p < 4; p++)
            cp16(st + sBo + p * 64 * ROWB, gB + (size_t)(p * 64) * K + k0);
        asm volatile("cp.async.commit_group;" ::: "memory");
    }

    int acc[4][4][4];
    #pragma unroll
    for (int mi = 0; mi < 4; mi++)
        #pragma unroll
        for (int ni = 0; ni < 4; ni++)
            #pragma unroll
            for (int c = 0; c < 4; c++) acc[mi][ni][c] = 0;

    const uint32_t aBase = (uint32_t)(wm + (l % 16)) * ROWB + (l / 16) * 16;
    const uint32_t bBase = BM * ROWB +
        (uint32_t)(wn + (l & 7) + ((l >> 4) & 1) * 8) * ROWB + ((l >> 3) & 1) * 16;

    for (int i = 0; i < nk; i++) {
        asm volatile("cp.async.wait_group %0;" :: "n"(STG - 2));
        __syncthreads();

        const int j = i + STG - 1;
        if (j < nk) {
            const uint32_t st = sb + (j % STG) * ST_BYTES;
            const int k0 = j * BKK;
            #pragma unroll
            for (int p = 0; p < 2; p++)
                cp16(st + sAo + p * 64 * ROWB, gA + (size_t)(p * 64) * K + k0);
            #pragma unroll
            for (int p = 0; p < 4; p++)
                cp16(st + sBo + p * 64 * ROWB, gB + (size_t)(p * 64) * K + k0);
        }
        asm volatile("cp.async.commit_group;" ::: "memory");

        const uint32_t st = sb + (i % STG) * ST_BYTES;
        #pragma unroll
        for (int ksub = 0; ksub < 4; ksub++) {
            uint32_t aF[4][4], bR[2][4];
            const uint32_t ka = st + aBase + ksub * 32;
            const uint32_t kb = st + bBase + ksub * 32;
            #pragma unroll
            for (int mi = 0; mi < 4; mi++) ldsm4(ka + mi * 16 * ROWB, aF[mi]);
            #pragma unroll
            for (int nq = 0; nq < 2; nq++) ldsm4(kb + nq * 16 * ROWB, bR[nq]);
            #pragma unroll
            for (int mi = 0; mi < 4; mi++)
                #pragma unroll
                for (int nq = 0; nq < 2; nq++) {
                    mma_s8(acc[mi][nq * 2],     aF[mi], &bR[nq][0]);
                    mma_s8(acc[mi][nq * 2 + 1], aF[mi], &bR[nq][2]);
                }
        }
    }

    #pragma unroll
    for (int mi = 0; mi < 4; mi++) {
        const int r0 = m0 + wm + mi * 16 + (l >> 2);
        const float sc0 = (mode == 2) ? g_oscale[r0]     : 1.f;
        const float sc1 = (mode == 2) ? g_oscale[r0 + 8] : 1.f;
        #pragma unroll
        for (int ni = 0; ni < 4; ni++) {
            const int c = n0 + wn + ni * 8 + (l & 3) * 2;
            float2 v0 = make_float2((float)acc[mi][ni][0] * sc0, (float)acc[mi][ni][1] * sc0);
            float2 v1 = make_float2((float)acc[mi][ni][2] * sc1, (float)acc[mi][ni][3] * sc1);
            *(float2*)(C + (size_t)r0 * N + c)       = v0;
            *(float2*)(C + (size_t)(r0 + 8) * N + c) = v1;
        }
    }
}

// ---------------- host ----------------
extern "C" void kernel_launch(void* const* d_in, const int* in_sizes, int n_in,
                              void* d_out, int out_size) {
    const float* x  = (const float*)d_in[0];
    const float* w1 = (const float*)d_in[1];
    const float* w2 = (const float*)d_in[2];
    float* out = (float*)d_out;

    void *pxq, *pw1q, *pw2q, *ph, *phq;
    cudaGetSymbolAddress(&pxq, g_xq);
    cudaGetSymbolAddress(&pw1q, g_w1q);
    cudaGetSymbolAddress(&pw2q, g_w2q);
    cudaGetSymbolAddress(&ph, g_h);
    cudaGetSymbolAddress(&phq, g_hq);

    cudaFuncSetAttribute(gemm_s8, cudaFuncAttributeMaxDynamicSharedMemorySize, GEMM_SMEM);

    cudaStream_t S = cudaStreamPerThread;
    cudaEvent_t eFork, eX, eW2;
    cudaEventCreateWithFlags(&eFork, cudaEventDisableTiming);
    cudaEventCreateWithFlags(&eX,  cudaEventDisableTiming);
    cudaEventCreateWithFlags(&eW2, cudaEventDisableTiming);

    // fork side stream at t=0: xquant ∥ w1 chain, then w2 chain
    cudaEventRecord(eFork, 0);
    cudaStreamWaitEvent(S, eFork, 0);
    xquant<<<MTOK, 256, 0, S>>>(x);
    cudaEventRecord(eX, S);
    absmean_partial<<<1024, 256, 0, S>>>(w2, 1);
    wquant<<<NW / (512 * 4), 256, 0, S>>>(w2, (int8_t*)pw2q, 1);
    cudaEventRecord(eW2, S);

    // main: w1 chain -> full gemm1 -> hquant -> full gemm2
    absmean_partial<<<1024, 256>>>(w1, 0);
    wquant<<<NW / (512 * 4), 256>>>(w1, (int8_t*)pw1q, 0);
    cudaStreamWaitEvent(0, eX, 0);
    gemm_s8<<<dim3(D1 / BN, MTOK / BM), 512, GEMM_SMEM>>>(      // full gemm1
        (const int8_t*)pxq, (const int8_t*)pw1q, (float*)ph, D0, D1, 1);
    cudaStreamWaitEvent(0, eW2, 0);
    hquant<<<MTOK, 256>>>();
    gemm_s8<<<dim3(D0 / BN, MTOK / BM), 512, GEMM_SMEM>>>(      // full gemm2
        (const int8_t*)phq, (const int8_t*)pw2q, out, D1, D0, 2);
}